// round 1
// baseline (speedup 1.0000x reference)
#include <cuda_runtime.h>

#define MODS   3
#define HEADS  4
#define HID    64
#define G      256
#define MAXN   50000
#define MAXE   250000

// ---------------- scratch (device globals; no allocation allowed) ----------------
static __device__ __align__(256) float d_h   [MODS * MAXN * HID];   // layer input features
static __device__ __align__(256) float d_hp  [MODS * MAXN * HID];   // projected features
static __device__ __align__(256) float d_acc [MODS * MAXN * HID];   // aggregation accumulator
static __device__ __align__(256) float d_logit[9ll * MAXE * HEADS]; // per-edge logits, reused for exp(a)
static __device__ __align__(256) float d_m   [9 * MAXN * HEADS];    // segment max
static __device__ __align__(256) float d_s   [9 * MAXN * HEADS];    // segment sum
static __device__ int   d_start[MODS * G];
static __device__ float d_pool [G * HID];
static __device__ float d_cnt  [G];

// ---------------- helpers ----------------
static __device__ __forceinline__ void atomicMaxF(float* addr, float val) {
    int cur = __float_as_int(*addr);
    while (__int_as_float(cur) < val) {
        int old = atomicCAS((int*)addr, cur, __float_as_int(val));
        if (old == cur) break;
        cur = old;
    }
}

// ---------------- init kernels ----------------
__global__ void k_init_start() {
    int i = blockIdx.x * blockDim.x + threadIdx.x;
    if (i < MODS * G) d_start[i] = 0x7fffffff;
}

__global__ void k_start_min(const int* __restrict__ b0, const int* __restrict__ b1,
                            const int* __restrict__ b2, int n) {
    int i = blockIdx.x * blockDim.x + threadIdx.x;
    if (i >= n) return;
    const int* b = (blockIdx.y == 0) ? b0 : (blockIdx.y == 1) ? b1 : b2;
    atomicMin(&d_start[blockIdx.y * G + b[i]], i);
}

// ---------------- input projection + positional encoding ----------------
template<int IN>
__global__ void k_input_proj(const float* __restrict__ x, const float* __restrict__ W,
                             const float* __restrict__ b, const int* __restrict__ batch,
                             int mod, int n)
{
    __shared__ float xs[8][IN];
    int node0 = blockIdx.x * 8;
    int tid = threadIdx.y * 64 + threadIdx.x;
    for (int idx = tid; idx < 8 * IN; idx += 512) {
        int r = idx / IN, k = idx - r * IN;
        int node = node0 + r;
        xs[r][k] = (node < n) ? x[(size_t)node * IN + k] : 0.f;
    }
    __syncthreads();
    int node = node0 + threadIdx.y;
    if (node >= n) return;
    int c = threadIdx.x;
    float acc = b[c];
    #pragma unroll 4
    for (int k = 0; k < IN; k++) acc = fmaf(xs[threadIdx.y][k], W[k * HID + c], acc);
    // positional encoding
    int posn = node - d_start[mod * G + batch[node]];
    int kk = c >> 1;
    float div = expf(-(float)(2 * kk) * (9.210340371976184f / 64.0f)); // ln(10000)/H
    float ang = (float)posn * div;
    float pe = (c & 1) ? cosf(ang) : sinf(ang);
    d_h[((size_t)mod * n + node) * HID + c] = acc + pe;
}

// ---------------- per-layer node projection (64x64 GEMM, all 3 modalities) ----------------
__global__ void k_node_proj(const float* __restrict__ Wl, const float* __restrict__ bl, int n)
{
    __shared__ float hs[8][HID];
    int m = blockIdx.y;
    const float* __restrict__ W = Wl + m * HID * HID;
    const float* __restrict__ b = bl + m * HID;
    int node0 = blockIdx.x * 8;
    int node = node0 + threadIdx.y;
    int c = threadIdx.x;
    hs[threadIdx.y][c] = (node < n) ? d_h[((size_t)m * n + node) * HID + c] : 0.f;
    __syncthreads();
    if (node >= n) return;
    float acc = b[c];
    #pragma unroll
    for (int k = 0; k < HID; k++) acc = fmaf(hs[threadIdx.y][k], W[k * HID + c], acc);
    d_hp[((size_t)m * n + node) * HID + c] = acc;
}

// ---------------- per-layer init of m / s / acc ----------------
__global__ void k_init_layer(int n)
{
    int i = blockIdx.x * blockDim.x + threadIdx.x;
    if (i < 9 * n * HEADS) { d_m[i] = -3.0e38f; d_s[i] = 0.f; }
    if (i < MODS * n * HID) d_acc[i] = 0.f;
}

// ---------------- pass A: logits + segment max (all 9 relations via blockIdx.y) ----------------
__global__ void k_passA(const int* __restrict__ edges, const float* __restrict__ attL,
                        int n, int E)
{
    int rel = blockIdx.y;
    int gtid = blockIdx.x * blockDim.x + threadIdx.x;
    int e = gtid >> 4;
    bool valid = e < E;
    int ec = valid ? e : 0;
    int t = threadIdx.x & 15;
    int mi = rel / 3, mj = rel % 3;
    const int* src = edges + (size_t)rel * 2 * E;
    const int* dst = src + E;
    int sN = src[ec], dN = dst[ec];
    float4 a4 = ((const float4*)(attL + rel * HID))[t];
    float4 hs = ((const float4*)(d_hp + ((size_t)mi * n + sN) * HID))[t];
    float4 hd = ((const float4*)(d_hp + ((size_t)mj * n + dN) * HID))[t];
    float p, z;
    z = hs.x + hd.x; z = z > 0.f ? z : 0.2f * z; p  = z * a4.x;
    z = hs.y + hd.y; z = z > 0.f ? z : 0.2f * z; p += z * a4.y;
    z = hs.z + hd.z; z = z > 0.f ? z : 0.2f * z; p += z * a4.z;
    z = hs.w + hd.w; z = z > 0.f ? z : 0.2f * z; p += z * a4.w;
    p += __shfl_xor_sync(0xffffffffu, p, 1);
    p += __shfl_xor_sync(0xffffffffu, p, 2);
    if (valid && (t & 3) == 0) {
        int head = t >> 2;
        d_logit[((size_t)rel * E + e) * HEADS + head] = p;
        atomicMaxF(&d_m[((size_t)rel * n + dN) * HEADS + head], p);
    }
}

// ---------------- pass B: exp + segment sum ----------------
__global__ void k_passB(const int* __restrict__ edges, int n, int E)
{
    int rel = blockIdx.y;
    int idx = blockIdx.x * blockDim.x + threadIdx.x;
    if (idx >= E * HEADS) return;
    int e = idx >> 2, head = idx & 3;
    const int* dst = edges + (size_t)rel * 2 * E + E;
    int dN = dst[e];
    size_t li = ((size_t)rel * E + e) * HEADS + head;
    float a = expf(d_logit[li] - d_m[((size_t)rel * n + dN) * HEADS + head]);
    d_logit[li] = a;
    atomicAdd(&d_s[((size_t)rel * n + dN) * HEADS + head], a);
}

// ---------------- pass C: weighted scatter-aggregate ----------------
__global__ void k_passC(const int* __restrict__ edges, int n, int E)
{
    int rel = blockIdx.y;
    int gtid = blockIdx.x * blockDim.x + threadIdx.x;
    int e = gtid >> 4;
    bool valid = e < E;
    int ec = valid ? e : 0;
    int t = threadIdx.x & 15;
    int head = t >> 2;
    int lane = threadIdx.x & 31;
    int mi = rel / 3, mj = rel % 3;
    const int* src = edges + (size_t)rel * 2 * E;
    const int* dst = src + E;
    int sN = src[ec], dN = dst[ec];
    float alpha = 0.f;
    if ((t & 3) == 0)
        alpha = d_logit[((size_t)rel * E + ec) * HEADS + head] /
                d_s[((size_t)rel * n + dN) * HEADS + head];
    alpha = __shfl_sync(0xffffffffu, alpha, lane & ~3);
    float4 hs = ((const float4*)(d_hp + ((size_t)mi * n + sN) * HID))[t];
    if (valid) {
        float* a = d_acc + ((size_t)mj * n + dN) * HID + t * 4;
        atomicAdd(a + 0, alpha * hs.x);
        atomicAdd(a + 1, alpha * hs.y);
        atomicAdd(a + 2, alpha * hs.z);
        atomicAdd(a + 3, alpha * hs.w);
    }
}

// ---------------- finalize layer: h = relu(acc/3) ----------------
__global__ void k_finalize(int n)
{
    int i = blockIdx.x * blockDim.x + threadIdx.x;
    if (i >= MODS * n * HID) return;
    float v = d_acc[i] * (1.f / 3.f);
    d_h[i] = v > 0.f ? v : 0.f;
}

// ---------------- pooling ----------------
__global__ void k_pool_zero()
{
    int i = blockIdx.x * blockDim.x + threadIdx.x;
    if (i < G * HID) d_pool[i] = 0.f;
    if (i < G) d_cnt[i] = 0.f;
}

__global__ void k_pool(const int* __restrict__ b0, const int* __restrict__ b1,
                       const int* __restrict__ b2, int n)
{
    const int CH = 128;
    int m = blockIdx.y;
    const int* batch = (m == 0) ? b0 : (m == 1) ? b1 : b2;
    const float* h = d_h + (size_t)m * n * HID;
    int i0 = blockIdx.x * CH;
    int c = threadIdx.x;
    int end = min(i0 + CH, n);
    float acc = 0.f; int cur = -1; int run = 0;
    for (int i = i0; i < end; i++) {
        int bg = batch[i];
        if (bg != cur) {
            if (cur >= 0) {
                atomicAdd(&d_pool[cur * HID + c], acc);
                if (c == 0) atomicAdd(&d_cnt[cur], (float)run);
            }
            cur = bg; acc = 0.f; run = 0;
        }
        acc += h[(size_t)i * HID + c];
        run++;
    }
    if (cur >= 0) {
        atomicAdd(&d_pool[cur * HID + c], acc);
        if (c == 0) atomicAdd(&d_cnt[cur], (float)run);
    }
}

// ---------------- readout MLP ----------------
__global__ void k_mlp(const float* __restrict__ Wf1, const float* __restrict__ bf1,
                      const float* __restrict__ Wf2, const float* __restrict__ bf2,
                      const float* __restrict__ Wf3, const float* __restrict__ bf3,
                      float* __restrict__ out)
{
    int g = threadIdx.x; // 256 threads, 1 block
    float inv = 1.f / fmaxf(d_cnt[g], 1.f);
    float y1[16];
    #pragma unroll
    for (int j = 0; j < 16; j++) y1[j] = bf1[j];
    for (int k = 0; k < HID; k++) {
        float v = d_pool[g * HID + k] * inv;
        #pragma unroll
        for (int j = 0; j < 16; j++) y1[j] = fmaf(v, Wf1[k * 16 + j], y1[j]);
    }
    float y2[16];
    #pragma unroll
    for (int j = 0; j < 16; j++) y2[j] = bf2[j];
    #pragma unroll
    for (int k = 0; k < 16; k++) {
        float v = y1[k] > 0.f ? y1[k] : 0.f;
        #pragma unroll
        for (int j = 0; j < 16; j++) y2[j] = fmaf(v, Wf2[k * 16 + j], y2[j]);
    }
    float o = bf3[0];
    #pragma unroll
    for (int j = 0; j < 16; j++) {
        float v = y2[j] > 0.f ? y2[j] : 0.f;
        o = fmaf(v, Wf3[j], o);
    }
    out[g] = o;
}

// ---------------- host launcher ----------------
extern "C" void kernel_launch(void* const* d_in, const int* in_sizes, int n_in,
                              void* d_out, int out_size)
{
    const float *x_text = 0, *x_audio = 0, *x_video = 0;
    const float *Wi_text = 0, *Wi_audio = 0, *Wi_video = 0;
    const float *bi[3] = {0, 0, 0};
    const float *Wn = 0, *bn = 0, *att = 0;
    const float *Wf1 = 0, *bf1 = 0, *Wf2 = 0, *bf2 = 0, *Wf3 = 0, *bf3 = 0;
    const int *batch[3] = {0, 0, 0};
    const int *edges = 0;
    int nb = 0, nbi = 0, n16 = 0;

    for (int i = 0; i < n_in; i++) {
        int s = in_sizes[i];
        const void* p = d_in[i];
        if      (s == 50000 * 300) x_text  = (const float*)p;
        else if (s == 50000 * 74)  x_audio = (const float*)p;
        else if (s == 50000 * 35)  x_video = (const float*)p;
        else if (s == 50000)       { if (nb < 3) batch[nb++] = (const int*)p; }
        else if (s == 9 * 2 * 250000) edges = (const int*)p;
        else if (s == 300 * 64)    Wi_text  = (const float*)p;
        else if (s == 74 * 64)     Wi_audio = (const float*)p;
        else if (s == 35 * 64)     Wi_video = (const float*)p;
        else if (s == 64)          { if (nbi < 3) bi[nbi++] = (const float*)p; }
        else if (s == 2 * 3 * 64 * 64) Wn = (const float*)p;
        else if (s == 2 * 3 * 64)  bn  = (const float*)p;
        else if (s == 2 * 9 * 64)  att = (const float*)p;
        else if (s == 64 * 16)     Wf1 = (const float*)p;
        else if (s == 16)          { if (n16 == 0) bf1 = (const float*)p;
                                     else if (n16 == 1) bf2 = (const float*)p;
                                     else Wf3 = (const float*)p; n16++; }
        else if (s == 16 * 16)     Wf2 = (const float*)p;
        else if (s == 1)           bf3 = (const float*)p;
    }

    const int n = MAXN, E = MAXE;

    // graph-segment starts (batch arrays are sorted)
    k_init_start<<<(MODS * G + 255) / 256, 256>>>();
    k_start_min<<<dim3((n + 255) / 256, 3), 256>>>(batch[0], batch[1], batch[2], n);

    // input projections + PE
    dim3 bProj(64, 8);
    k_input_proj<300><<<(n + 7) / 8, bProj>>>(x_text,  Wi_text,  bi[0], batch[0], 0, n);
    k_input_proj<74> <<<(n + 7) / 8, bProj>>>(x_audio, Wi_audio, bi[1], batch[1], 1, n);
    k_input_proj<35> <<<(n + 7) / 8, bProj>>>(x_video, Wi_video, bi[2], batch[2], 2, n);

    // GAT layers
    for (int l = 0; l < 2; l++) {
        k_node_proj<<<dim3((n + 7) / 8, 3), bProj>>>(Wn + (size_t)l * 3 * HID * HID,
                                                     bn + (size_t)l * 3 * HID, n);
        k_init_layer<<<(MODS * n * HID + 255) / 256, 256>>>(n);
        dim3 gA((E * 16 + 255) / 256, 9);
        k_passA<<<gA, 256>>>(edges, att + (size_t)l * 9 * HID, n, E);
        k_passB<<<dim3((E * HEADS + 255) / 256, 9), 256>>>(edges, n, E);
        k_passC<<<gA, 256>>>(edges, n, E);
        k_finalize<<<(MODS * n * HID + 255) / 256, 256>>>(n);
    }

    // pooling + MLP head
    k_pool_zero<<<(G * HID + 255) / 256, 256>>>();
    k_pool<<<dim3((n + 127) / 128, 3), 64>>>(batch[0], batch[1], batch[2], n);
    k_mlp<<<1, 256>>>(Wf1, bf1, Wf2, bf2, Wf3, bf3, (float*)d_out);
}

// round 6
// speedup vs baseline: 1.5879x; 1.5879x over previous
#include <cuda_runtime.h>

#define MODS   3
#define HEADS  4
#define HID    64
#define G      256
#define MAXN   50000
#define MAXE   250000
#define PELEN  5000

// ---------------- scratch (device globals; no allocation allowed) ----------------
static __device__ __align__(256) float d_h  [MODS * MAXN * HID];  // layer features
static __device__ __align__(256) float d_hp [MODS * MAXN * HID];  // projected features
static __device__ int   d_deg   [9 * MAXN];
static __device__ int   d_rowptr[9 * (MAXN + 1)];
static __device__ int   d_cursor[9 * MAXN];
static __device__ int   d_esrc  [9 * MAXE];
static __device__ int   d_start [MODS * G];
static __device__ float d_pool  [G * HID];
static __device__ float d_cnt   [G];

// ---------------- init: zero degree hist + pool + start sentinel ----------------
__global__ void k_init()
{
    int i = blockIdx.x * blockDim.x + threadIdx.x;
    if (i < 9 * MAXN) d_deg[i] = 0;
    if (i < MODS * G) d_start[i] = 0x7fffffff;
    if (i < G * HID)  d_pool[i] = 0.f;
    if (i < G)        d_cnt[i] = 0.f;
}

__global__ void k_start_min(const int* __restrict__ b0, const int* __restrict__ b1,
                            const int* __restrict__ b2, int n)
{
    int i = blockIdx.x * blockDim.x + threadIdx.x;
    if (i >= n) return;
    const int* b = (blockIdx.y == 0) ? b0 : (blockIdx.y == 1) ? b1 : b2;
    atomicMin(&d_start[blockIdx.y * G + b[i]], i);
}

// ---------------- input projection + positional encoding (R1-proven form) ----------------
template<int IN>
__global__ void k_input_proj(const float* __restrict__ x, const float* __restrict__ W,
                             const float* __restrict__ b, const int* __restrict__ batch,
                             int mod, int n)
{
    __shared__ float xs[8][IN];
    int node0 = blockIdx.x * 8;
    int tid = threadIdx.y * 64 + threadIdx.x;
    for (int idx = tid; idx < 8 * IN; idx += 512) {
        int r = idx / IN, k = idx - r * IN;
        int node = node0 + r;
        xs[r][k] = (node < n) ? x[(size_t)node * IN + k] : 0.f;
    }
    __syncthreads();
    int node = node0 + threadIdx.y;
    if (node >= n) return;
    int c = threadIdx.x;
    float acc = b[c];
    #pragma unroll 4
    for (int k = 0; k < IN; k++) acc = fmaf(xs[threadIdx.y][k], W[k * HID + c], acc);
    // positional encoding (inline, same as R1 which passed)
    int posn = node - d_start[mod * G + batch[node]];
    int kk = c >> 1;
    float div = expf(-(float)(2 * kk) * (9.210340371976184f / 64.0f)); // ln(1e4)/64
    float ang = (float)posn * div;
    float pe = (c & 1) ? cosf(ang) : sinf(ang);
    d_h[((size_t)mod * n + node) * HID + c] = acc + pe;
}

// ---------------- per-layer node projection (R1-proven form) ----------------
__global__ void k_node_proj(const float* __restrict__ Wl, const float* __restrict__ bl, int n)
{
    __shared__ float hs[8][HID];
    int m = blockIdx.y;
    const float* __restrict__ W = Wl + m * HID * HID;
    const float* __restrict__ b = bl + m * HID;
    int node0 = blockIdx.x * 8;
    int node = node0 + threadIdx.y;
    int c = threadIdx.x;
    hs[threadIdx.y][c] = (node < n) ? d_h[((size_t)m * n + node) * HID + c] : 0.f;
    __syncthreads();
    if (node >= n) return;
    float acc = b[c];
    #pragma unroll
    for (int k = 0; k < HID; k++) acc = fmaf(hs[threadIdx.y][k], W[k * HID + c], acc);
    d_hp[((size_t)m * n + node) * HID + c] = acc;
}

// ---------------- CSR build ----------------
__global__ void k_hist(const int* __restrict__ edges, int E)
{
    int rel = blockIdx.y;
    int e = blockIdx.x * blockDim.x + threadIdx.x;
    if (e >= E) return;
    int dN = edges[(size_t)rel * 2 * E + E + e];
    atomicAdd(&d_deg[rel * MAXN + dN], 1);
}

__global__ void k_scan(int n)   // 9 blocks x 256 threads
{
    __shared__ int sh[256];
    const int CH = (MAXN + 255) / 256;    // 196
    int rel = blockIdx.x;
    int t = threadIdx.x;
    const int* deg = d_deg + rel * MAXN;
    int base = t * CH;
    int sum = 0;
    for (int k = 0; k < CH; k++) { int idx = base + k; if (idx < n) sum += deg[idx]; }
    sh[t] = sum;
    __syncthreads();
    for (int off = 1; off < 256; off <<= 1) {
        int v = (t >= off) ? sh[t - off] : 0;
        __syncthreads();
        sh[t] += v;
        __syncthreads();
    }
    int run = (t == 0) ? 0 : sh[t - 1];
    int* rp = d_rowptr + rel * (MAXN + 1);
    int* cu = d_cursor + rel * MAXN;
    for (int k = 0; k < CH; k++) {
        int idx = base + k;
        if (idx < n) { int d = deg[idx]; rp[idx] = run; cu[idx] = run; run += d; }
    }
    if (t == 255) rp[n] = sh[255];
}

__global__ void k_scatter(const int* __restrict__ edges, int E)
{
    int rel = blockIdx.y;
    int e = blockIdx.x * blockDim.x + threadIdx.x;
    if (e >= E) return;
    const int* src = edges + (size_t)rel * 2 * E;
    int sN = src[e], dN = src[E + e];
    int pos = atomicAdd(&d_cursor[rel * MAXN + dN], 1);
    d_esrc[(size_t)rel * E + pos] = sN;
}

// ---------------- GAT layer: warp per (dst-modality j, dst node), no atomics ----------------
__global__ void k_gat(const float* __restrict__ attL, int n)
{
    int wid = threadIdx.x >> 5, lane = threadIdx.x & 31;
    int dst = blockIdx.x * 8 + wid;
    if (dst >= n) return;
    int j = blockIdx.y;
    int l2 = lane * 2;

    float2 hd = *(const float2*)&d_hp[((size_t)j * n + dst) * HID + l2];
    float accx = 0.f, accy = 0.f;

    for (int i = 0; i < MODS; i++) {
        int rel = i * 3 + j;
        int rs = d_rowptr[rel * (MAXN + 1) + dst];
        int re = d_rowptr[rel * (MAXN + 1) + dst + 1];
        if (rs == re) continue;
        float2 a2 = *(const float2*)&attL[rel * HID + l2];
        const float* __restrict__ hpB = d_hp + (size_t)i * n * HID;
        const int* __restrict__ es = d_esrc + (size_t)rel * MAXE;

        // pass 1: online softmax stats (m, s per head, replicated across 8-lane group)
        float m = -3.0e38f, s = 0.f;
        for (int p = rs; p < re; p++) {
            int src = es[p];
            float2 hs = *(const float2*)&hpB[(size_t)src * HID + l2];
            float zx = hs.x + hd.x; zx = zx > 0.f ? zx : 0.2f * zx;
            float zy = hs.y + hd.y; zy = zy > 0.f ? zy : 0.2f * zy;
            float t = zx * a2.x + zy * a2.y;
            t += __shfl_xor_sync(0xffffffffu, t, 1);
            t += __shfl_xor_sync(0xffffffffu, t, 2);
            t += __shfl_xor_sync(0xffffffffu, t, 4);
            float m2 = fmaxf(m, t);
            s = s * __expf(m - m2) + __expf(t - m2);
            m = m2;
        }
        float inv_s = 1.f / s;

        // pass 2: recompute logit, aggregate alpha * hs
        for (int p = rs; p < re; p++) {
            int src = es[p];
            float2 hs = *(const float2*)&hpB[(size_t)src * HID + l2];
            float zx = hs.x + hd.x; zx = zx > 0.f ? zx : 0.2f * zx;
            float zy = hs.y + hd.y; zy = zy > 0.f ? zy : 0.2f * zy;
            float t = zx * a2.x + zy * a2.y;
            t += __shfl_xor_sync(0xffffffffu, t, 1);
            t += __shfl_xor_sync(0xffffffffu, t, 2);
            t += __shfl_xor_sync(0xffffffffu, t, 4);
            float alpha = __expf(t - m) * inv_s;
            accx = fmaf(alpha, hs.x, accx);
            accy = fmaf(alpha, hs.y, accy);
        }
    }

    float ox = accx * (1.f / 3.f); ox = ox > 0.f ? ox : 0.f;
    float oy = accy * (1.f / 3.f); oy = oy > 0.f ? oy : 0.f;
    float2 o = {ox, oy};
    *(float2*)&d_h[((size_t)j * n + dst) * HID + l2] = o;
}

// ---------------- pooling (R1-proven form) ----------------
__global__ void k_pool(const int* __restrict__ b0, const int* __restrict__ b1,
                       const int* __restrict__ b2, int n)
{
    const int CH = 128;
    int m = blockIdx.y;
    const int* batch = (m == 0) ? b0 : (m == 1) ? b1 : b2;
    const float* h = d_h + (size_t)m * n * HID;
    int i0 = blockIdx.x * CH;
    int c = threadIdx.x;
    int end = min(i0 + CH, n);
    float acc = 0.f; int cur = -1; int run = 0;
    for (int i = i0; i < end; i++) {
        int bg = batch[i];
        if (bg != cur) {
            if (cur >= 0) {
                atomicAdd(&d_pool[cur * HID + c], acc);
                if (c == 0) atomicAdd(&d_cnt[cur], (float)run);
            }
            cur = bg; acc = 0.f; run = 0;
        }
        acc += h[(size_t)i * HID + c];
        run++;
    }
    if (cur >= 0) {
        atomicAdd(&d_pool[cur * HID + c], acc);
        if (c == 0) atomicAdd(&d_cnt[cur], (float)run);
    }
}

// ---------------- readout MLP (R1-proven form) ----------------
__global__ void k_mlp(const float* __restrict__ Wf1, const float* __restrict__ bf1,
                      const float* __restrict__ Wf2, const float* __restrict__ bf2,
                      const float* __restrict__ Wf3, const float* __restrict__ bf3,
                      float* __restrict__ out)
{
    int g = threadIdx.x; // 256 threads, 1 block
    float inv = 1.f / fmaxf(d_cnt[g], 1.f);
    float y1[16];
    #pragma unroll
    for (int j = 0; j < 16; j++) y1[j] = bf1[j];
    for (int k = 0; k < HID; k++) {
        float v = d_pool[g * HID + k] * inv;
        #pragma unroll
        for (int j = 0; j < 16; j++) y1[j] = fmaf(v, Wf1[k * 16 + j], y1[j]);
    }
    float y2[16];
    #pragma unroll
    for (int j = 0; j < 16; j++) y2[j] = bf2[j];
    #pragma unroll
    for (int k = 0; k < 16; k++) {
        float v = y1[k] > 0.f ? y1[k] : 0.f;
        #pragma unroll
        for (int j = 0; j < 16; j++) y2[j] = fmaf(v, Wf2[k * 16 + j], y2[j]);
    }
    float o = bf3[0];
    #pragma unroll
    for (int j = 0; j < 16; j++) {
        float v = y2[j] > 0.f ? y2[j] : 0.f;
        o = fmaf(v, Wf3[j], o);
    }
    out[g] = o;
}

// ---------------- host launcher ----------------
extern "C" void kernel_launch(void* const* d_in, const int* in_sizes, int n_in,
                              void* d_out, int out_size)
{
    const float *x_text = 0, *x_audio = 0, *x_video = 0;
    const float *Wi_text = 0, *Wi_audio = 0, *Wi_video = 0;
    const float *bi[3] = {0, 0, 0};
    const float *Wn = 0, *bn = 0, *att = 0;
    const float *Wf1 = 0, *bf1 = 0, *Wf2 = 0, *bf2 = 0, *Wf3 = 0, *bf3 = 0;
    const int *batch[3] = {0, 0, 0};
    const int *edges = 0;
    int nb = 0, nbi = 0, n16 = 0;

    for (int i = 0; i < n_in; i++) {
        int s = in_sizes[i];
        const void* p = d_in[i];
        if      (s == 50000 * 300) x_text  = (const float*)p;
        else if (s == 50000 * 74)  x_audio = (const float*)p;
        else if (s == 50000 * 35)  x_video = (const float*)p;
        else if (s == 50000)       { if (nb < 3) batch[nb++] = (const int*)p; }
        else if (s == 9 * 2 * 250000) edges = (const int*)p;
        else if (s == 300 * 64)    Wi_text  = (const float*)p;
        else if (s == 74 * 64)     Wi_audio = (const float*)p;
        else if (s == 35 * 64)     Wi_video = (const float*)p;
        else if (s == 64)          { if (nbi < 3) bi[nbi++] = (const float*)p; }
        else if (s == 2 * 3 * 64 * 64) Wn = (const float*)p;
        else if (s == 2 * 3 * 64)  bn  = (const float*)p;
        else if (s == 2 * 9 * 64)  att = (const float*)p;
        else if (s == 64 * 16)     Wf1 = (const float*)p;
        else if (s == 16)          { if (n16 == 0) bf1 = (const float*)p;
                                     else if (n16 == 1) bf2 = (const float*)p;
                                     else Wf3 = (const float*)p; n16++; }
        else if (s == 16 * 16)     Wf2 = (const float*)p;
        else if (s == 1)           bf3 = (const float*)p;
    }

    const int n = MAXN, E = MAXE;

    // init + segment starts
    k_init<<<(9 * MAXN + 255) / 256, 256>>>();
    k_start_min<<<dim3((n + 255) / 256, 3), 256>>>(batch[0], batch[1], batch[2], n);

    // CSR build (once; shared by both layers)
    k_hist<<<dim3((E + 255) / 256, 9), 256>>>(edges, E);
    k_scan<<<9, 256>>>(n);
    k_scatter<<<dim3((E + 255) / 256, 9), 256>>>(edges, E);

    // input projections + PE (R1-proven kernels)
    dim3 bProj(64, 8);
    k_input_proj<300><<<(n + 7) / 8, bProj>>>(x_text,  Wi_text,  bi[0], batch[0], 0, n);
    k_input_proj<74> <<<(n + 7) / 8, bProj>>>(x_audio, Wi_audio, bi[1], batch[1], 1, n);
    k_input_proj<35> <<<(n + 7) / 8, bProj>>>(x_video, Wi_video, bi[2], batch[2], 2, n);

    // GAT layers
    for (int l = 0; l < 2; l++) {
        k_node_proj<<<dim3((n + 7) / 8, 3), bProj>>>(Wn + (size_t)l * 3 * HID * HID,
                                                     bn + (size_t)l * 3 * HID, n);
        k_gat<<<dim3((n + 7) / 8, 3), 256>>>(att + (size_t)l * 9 * HID, n);
    }

    // pooling + MLP head
    k_pool<<<dim3((n + 127) / 128, 3), 64>>>(batch[0], batch[1], batch[2], n);
    k_mlp<<<1, 256>>>(Wf1, bf1, Wf2, bf2, Wf3, bf3, (float*)d_out);
}

// round 7
// speedup vs baseline: 2.2697x; 1.4294x over previous
#include <cuda_runtime.h>

#define MODS   3
#define HEADS  4
#define HID    64
#define G      256
#define MAXN   50000
#define MAXE   250000
#define TOTDEG (9 * MAXN)
#define SCAN_BLOCKS ((TOTDEG + 2047) / 2048)   // 220

// ---------------- scratch (device globals; no allocation allowed) ----------------
static __device__ __align__(256) float d_h  [MODS * MAXN * HID];  // layer features
static __device__ __align__(256) float d_hp [MODS * MAXN * HID];  // projected features
static __device__ __align__(16) int   d_deg   [TOTDEG];
static __device__ __align__(16) int   d_scantmp[TOTDEG];
static __device__ int   d_bsum  [SCAN_BLOCKS];
static __device__ int   d_rowptr[9 * (MAXN + 1)];
static __device__ int   d_cursor[9 * MAXN];
static __device__ int   d_esrc  [9 * MAXE];
static __device__ int   d_start [MODS * G];
static __device__ float d_pool  [G * HID];
static __device__ float d_cnt   [G];

// ---------------- init: zero degree hist + pool + start sentinel + rowptr tails ----------------
__global__ void k_init()
{
    int i = blockIdx.x * blockDim.x + threadIdx.x;
    if (i < TOTDEG)   d_deg[i] = 0;
    if (i < MODS * G) d_start[i] = 0x7fffffff;
    if (i < G * HID)  d_pool[i] = 0.f;
    if (i < G)        d_cnt[i] = 0.f;
    if (i < 9)        d_rowptr[i * (MAXN + 1) + MAXN] = MAXE;
}

__global__ void k_start_min(const int* __restrict__ b0, const int* __restrict__ b1,
                            const int* __restrict__ b2, int n)
{
    int i = blockIdx.x * blockDim.x + threadIdx.x;
    if (i >= n) return;
    const int* b = (blockIdx.y == 0) ? b0 : (blockIdx.y == 1) ? b1 : b2;
    atomicMin(&d_start[blockIdx.y * G + b[i]], i);
}

// ---------------- CSR build ----------------
__global__ void k_hist(const int* __restrict__ edges, int E)
{
    int rel = blockIdx.y;
    int e = blockIdx.x * blockDim.x + threadIdx.x;
    if (e >= E) return;
    int dN = edges[(size_t)rel * 2 * E + E + e];
    atomicAdd(&d_deg[rel * MAXN + dN], 1);
}

// phase A: per-block local exclusive scan (2048 elems/block), write block sums
__global__ void k_scanA()
{
    __shared__ int sh[256];
    int t = threadIdx.x;
    int base = blockIdx.x * 2048 + t * 8;
    int v0 = 0, v1 = 0, v2 = 0, v3 = 0, v4 = 0, v5 = 0, v6 = 0, v7 = 0;
    if (base + 7 < TOTDEG) {
        int4 a = *(const int4*)&d_deg[base];
        int4 b = *(const int4*)&d_deg[base + 4];
        v0 = a.x; v1 = a.y; v2 = a.z; v3 = a.w;
        v4 = b.x; v5 = b.y; v6 = b.z; v7 = b.w;
    } else {
        if (base + 0 < TOTDEG) v0 = d_deg[base + 0];
        if (base + 1 < TOTDEG) v1 = d_deg[base + 1];
        if (base + 2 < TOTDEG) v2 = d_deg[base + 2];
        if (base + 3 < TOTDEG) v3 = d_deg[base + 3];
        if (base + 4 < TOTDEG) v4 = d_deg[base + 4];
        if (base + 5 < TOTDEG) v5 = d_deg[base + 5];
        if (base + 6 < TOTDEG) v6 = d_deg[base + 6];
        if (base + 7 < TOTDEG) v7 = d_deg[base + 7];
    }
    int tsum = v0 + v1 + v2 + v3 + v4 + v5 + v6 + v7;
    sh[t] = tsum;
    __syncthreads();
    for (int off = 1; off < 256; off <<= 1) {
        int v = (t >= off) ? sh[t - off] : 0;
        __syncthreads();
        sh[t] += v;
        __syncthreads();
    }
    int run = sh[t] - tsum;   // exclusive offset within block
    if (t == 255) d_bsum[blockIdx.x] = sh[255];
    int w;
    w = run; run += v0; if (base + 0 < TOTDEG) d_scantmp[base + 0] = w;
    w = run; run += v1; if (base + 1 < TOTDEG) d_scantmp[base + 1] = w;
    w = run; run += v2; if (base + 2 < TOTDEG) d_scantmp[base + 2] = w;
    w = run; run += v3; if (base + 3 < TOTDEG) d_scantmp[base + 3] = w;
    w = run; run += v4; if (base + 4 < TOTDEG) d_scantmp[base + 4] = w;
    w = run; run += v5; if (base + 5 < TOTDEG) d_scantmp[base + 5] = w;
    w = run; run += v6; if (base + 6 < TOTDEG) d_scantmp[base + 6] = w;
    w = run; run += v7; if (base + 7 < TOTDEG) d_scantmp[base + 7] = w;
}

// phase B: single block scans the block sums (in place, exclusive)
__global__ void k_scanB()
{
    __shared__ int sh[256];
    int t = threadIdx.x;
    int v = (t < SCAN_BLOCKS) ? d_bsum[t] : 0;
    sh[t] = v;
    __syncthreads();
    for (int off = 1; off < 256; off <<= 1) {
        int x = (t >= off) ? sh[t - off] : 0;
        __syncthreads();
        sh[t] += x;
        __syncthreads();
    }
    if (t < SCAN_BLOCKS) d_bsum[t] = sh[t] - v;   // exclusive
}

// phase C: add block offsets, convert global prefix to per-relation rowptr/cursor
__global__ void k_scanC()
{
    int idx = blockIdx.x * blockDim.x + threadIdx.x;
    if (idx >= TOTDEG) return;
    int val = d_scantmp[idx] + d_bsum[idx >> 11];
    int rel = idx / MAXN;
    int loc = idx - rel * MAXN;
    int r = val - rel * MAXE;   // each relation has exactly E edges
    d_rowptr[rel * (MAXN + 1) + loc] = r;
    d_cursor[rel * MAXN + loc] = r;
}

__global__ void k_scatter(const int* __restrict__ edges, int E)
{
    int rel = blockIdx.y;
    int e = blockIdx.x * blockDim.x + threadIdx.x;
    if (e >= E) return;
    const int* src = edges + (size_t)rel * 2 * E;
    int sN = src[e], dN = src[E + e];
    int pos = atomicAdd(&d_cursor[rel * MAXN + dN], 1);
    d_esrc[(size_t)rel * E + pos] = sN;
}

// ---------------- input projection + PE: 16 nodes x 16 colgroups, float4 outputs ----------------
template<int IN>
__global__ void k_inproj(const float* __restrict__ x, const float* __restrict__ W,
                         const float* __restrict__ b, const int* __restrict__ batch,
                         int mod, int n)
{
    __shared__ float xs[16][IN];
    int tid = threadIdx.x;
    int node0 = blockIdx.x * 16;
    for (int idx = tid; idx < 16 * IN; idx += 256) {
        int r = idx / IN, k = idx - r * IN;
        int node = node0 + r;
        xs[r][k] = (node < n) ? x[(size_t)node * IN + k] : 0.f;
    }
    __syncthreads();
    int ty = tid >> 4, tx = tid & 15;
    int node = node0 + ty;
    if (node >= n) return;

    const float4* __restrict__ W4 = (const float4*)W;
    float4 acc = ((const float4*)b)[tx];
    #pragma unroll 4
    for (int k = 0; k < IN; k++) {
        float xv = xs[ty][k];
        float4 wv = W4[k * 16 + tx];
        acc.x = fmaf(xv, wv.x, acc.x);
        acc.y = fmaf(xv, wv.y, acc.y);
        acc.z = fmaf(xv, wv.z, acc.z);
        acc.w = fmaf(xv, wv.w, acc.w);
    }
    // positional encoding (R1-proven math)
    int posn = node - d_start[mod * G + batch[node]];
    float pf = (float)posn;
    int kk0 = 2 * tx, kk1 = 2 * tx + 1;
    float div0 = expf(-(float)(2 * kk0) * (9.210340371976184f / 64.0f));
    float div1 = expf(-(float)(2 * kk1) * (9.210340371976184f / 64.0f));
    float a0 = pf * div0, a1 = pf * div1;
    acc.x += sinf(a0);
    acc.y += cosf(a0);
    acc.z += sinf(a1);
    acc.w += cosf(a1);
    ((float4*)(d_h + ((size_t)mod * n + node) * HID))[tx] = acc;
}

// ---------------- node projection: same structure, 3 modalities via blockIdx.y ----------------
__global__ void k_nodeproj(const float* __restrict__ Wl, const float* __restrict__ bl, int n)
{
    __shared__ float xs[16][HID];
    int m = blockIdx.y;
    int tid = threadIdx.x;
    int node0 = blockIdx.x * 16;
    const float* __restrict__ src = d_h + (size_t)m * n * HID;
    for (int idx = tid; idx < 16 * HID; idx += 256) {
        int r = idx >> 6, k = idx & 63;
        int node = node0 + r;
        xs[r][k] = (node < n) ? src[(size_t)node * HID + k] : 0.f;
    }
    __syncthreads();
    int ty = tid >> 4, tx = tid & 15;
    int node = node0 + ty;
    if (node >= n) return;

    const float4* __restrict__ W4 = (const float4*)(Wl + m * HID * HID);
    float4 acc = ((const float4*)(bl + m * HID))[tx];
    #pragma unroll 4
    for (int k = 0; k < HID; k++) {
        float xv = xs[ty][k];
        float4 wv = W4[k * 16 + tx];
        acc.x = fmaf(xv, wv.x, acc.x);
        acc.y = fmaf(xv, wv.y, acc.y);
        acc.z = fmaf(xv, wv.z, acc.z);
        acc.w = fmaf(xv, wv.w, acc.w);
    }
    ((float4*)(d_hp + ((size_t)m * n + node) * HID))[tx] = acc;
}

// ---------------- GAT layer: warp per (dst-mod j, dst node); single-pass softmax ----------------
__global__ void k_gat(const float* __restrict__ attL, int n)
{
    int wid = threadIdx.x >> 5, lane = threadIdx.x & 31;
    int dst = blockIdx.x * 8 + wid;
    if (dst >= n) return;
    int j = blockIdx.y;
    int l2 = lane * 2;

    float2 hd = *(const float2*)&d_hp[((size_t)j * n + dst) * HID + l2];
    float accx = 0.f, accy = 0.f;

    for (int i = 0; i < MODS; i++) {
        int rel = i * 3 + j;
        int rs = d_rowptr[rel * (MAXN + 1) + dst];
        int re = d_rowptr[rel * (MAXN + 1) + dst + 1];
        if (rs == re) continue;
        float2 a2 = *(const float2*)&attL[rel * HID + l2];
        const float* __restrict__ hpB = d_hp + (size_t)i * n * HID;
        const int* __restrict__ es = d_esrc + (size_t)rel * MAXE;

        // single pass: s = sum exp(t), u = sum exp(t)*hs  (shift-free softmax; logits are tiny)
        float s = 0.f, ax = 0.f, ay = 0.f;
        for (int c0 = rs; c0 < re; c0 += 32) {
            int my = (c0 + lane < re) ? es[c0 + lane] : 0;
            int cnt = min(32, re - c0);
            for (int q = 0; q < cnt; q++) {
                int src = __shfl_sync(0xffffffffu, my, q);
                float2 hs = *(const float2*)&hpB[(size_t)src * HID + l2];
                float zx = hs.x + hd.x; zx = zx > 0.f ? zx : 0.2f * zx;
                float zy = hs.y + hd.y; zy = zy > 0.f ? zy : 0.2f * zy;
                float t = zx * a2.x + zy * a2.y;
                t += __shfl_xor_sync(0xffffffffu, t, 1);
                t += __shfl_xor_sync(0xffffffffu, t, 2);
                t += __shfl_xor_sync(0xffffffffu, t, 4);
                float e = __expf(t);
                s += e;
                ax = fmaf(e, hs.x, ax);
                ay = fmaf(e, hs.y, ay);
            }
        }
        float inv_s = 1.f / s;
        accx = fmaf(ax, inv_s, accx);
        accy = fmaf(ay, inv_s, accy);
    }

    float ox = accx * (1.f / 3.f); ox = ox > 0.f ? ox : 0.f;
    float oy = accy * (1.f / 3.f); oy = oy > 0.f ? oy : 0.f;
    float2 o = {ox, oy};
    *(float2*)&d_h[((size_t)j * n + dst) * HID + l2] = o;
}

// ---------------- pooling (R1-proven form) ----------------
__global__ void k_pool(const int* __restrict__ b0, const int* __restrict__ b1,
                       const int* __restrict__ b2, int n)
{
    const int CH = 128;
    int m = blockIdx.y;
    const int* batch = (m == 0) ? b0 : (m == 1) ? b1 : b2;
    const float* h = d_h + (size_t)m * n * HID;
    int i0 = blockIdx.x * CH;
    int c = threadIdx.x;
    int end = min(i0 + CH, n);
    float acc = 0.f; int cur = -1; int run = 0;
    for (int i = i0; i < end; i++) {
        int bg = batch[i];
        if (bg != cur) {
            if (cur >= 0) {
                atomicAdd(&d_pool[cur * HID + c], acc);
                if (c == 0) atomicAdd(&d_cnt[cur], (float)run);
            }
            cur = bg; acc = 0.f; run = 0;
        }
        acc += h[(size_t)i * HID + c];
        run++;
    }
    if (cur >= 0) {
        atomicAdd(&d_pool[cur * HID + c], acc);
        if (c == 0) atomicAdd(&d_cnt[cur], (float)run);
    }
}

// ---------------- readout MLP (R1-proven form) ----------------
__global__ void k_mlp(const float* __restrict__ Wf1, const float* __restrict__ bf1,
                      const float* __restrict__ Wf2, const float* __restrict__ bf2,
                      const float* __restrict__ Wf3, const float* __restrict__ bf3,
                      float* __restrict__ out)
{
    int g = threadIdx.x; // 256 threads, 1 block
    float inv = 1.f / fmaxf(d_cnt[g], 1.f);
    float y1[16];
    #pragma unroll
    for (int j = 0; j < 16; j++) y1[j] = bf1[j];
    for (int k = 0; k < HID; k++) {
        float v = d_pool[g * HID + k] * inv;
        #pragma unroll
        for (int j = 0; j < 16; j++) y1[j] = fmaf(v, Wf1[k * 16 + j], y1[j]);
    }
    float y2[16];
    #pragma unroll
    for (int j = 0; j < 16; j++) y2[j] = bf2[j];
    #pragma unroll
    for (int k = 0; k < 16; k++) {
        float v = y1[k] > 0.f ? y1[k] : 0.f;
        #pragma unroll
        for (int j = 0; j < 16; j++) y2[j] = fmaf(v, Wf2[k * 16 + j], y2[j]);
    }
    float o = bf3[0];
    #pragma unroll
    for (int j = 0; j < 16; j++) {
        float v = y2[j] > 0.f ? y2[j] : 0.f;
        o = fmaf(v, Wf3[j], o);
    }
    out[g] = o;
}

// ---------------- host launcher ----------------
extern "C" void kernel_launch(void* const* d_in, const int* in_sizes, int n_in,
                              void* d_out, int out_size)
{
    const float *x_text = 0, *x_audio = 0, *x_video = 0;
    const float *Wi_text = 0, *Wi_audio = 0, *Wi_video = 0;
    const float *bi[3] = {0, 0, 0};
    const float *Wn = 0, *bn = 0, *att = 0;
    const float *Wf1 = 0, *bf1 = 0, *Wf2 = 0, *bf2 = 0, *Wf3 = 0, *bf3 = 0;
    const int *batch[3] = {0, 0, 0};
    const int *edges = 0;
    int nb = 0, nbi = 0, n16 = 0;

    for (int i = 0; i < n_in; i++) {
        int s = in_sizes[i];
        const void* p = d_in[i];
        if      (s == 50000 * 300) x_text  = (const float*)p;
        else if (s == 50000 * 74)  x_audio = (const float*)p;
        else if (s == 50000 * 35)  x_video = (const float*)p;
        else if (s == 50000)       { if (nb < 3) batch[nb++] = (const int*)p; }
        else if (s == 9 * 2 * 250000) edges = (const int*)p;
        else if (s == 300 * 64)    Wi_text  = (const float*)p;
        else if (s == 74 * 64)     Wi_audio = (const float*)p;
        else if (s == 35 * 64)     Wi_video = (const float*)p;
        else if (s == 64)          { if (nbi < 3) bi[nbi++] = (const float*)p; }
        else if (s == 2 * 3 * 64 * 64) Wn = (const float*)p;
        else if (s == 2 * 3 * 64)  bn  = (const float*)p;
        else if (s == 2 * 9 * 64)  att = (const float*)p;
        else if (s == 64 * 16)     Wf1 = (const float*)p;
        else if (s == 16)          { if (n16 == 0) bf1 = (const float*)p;
                                     else if (n16 == 1) bf2 = (const float*)p;
                                     else Wf3 = (const float*)p; n16++; }
        else if (s == 16 * 16)     Wf2 = (const float*)p;
        else if (s == 1)           bf3 = (const float*)p;
    }

    const int n = MAXN, E = MAXE;
    const int nblk16 = (n + 15) / 16;

    // init + segment starts
    k_init<<<(TOTDEG + 255) / 256, 256>>>();
    k_start_min<<<dim3((n + 255) / 256, 3), 256>>>(batch[0], batch[1], batch[2], n);

    // CSR build (once; shared by both layers)
    k_hist<<<dim3((E + 255) / 256, 9), 256>>>(edges, E);
    k_scanA<<<SCAN_BLOCKS, 256>>>();
    k_scanB<<<1, 256>>>();
    k_scanC<<<(TOTDEG + 255) / 256, 256>>>();
    k_scatter<<<dim3((E + 255) / 256, 9), 256>>>(edges, E);

    // input projections + PE
    k_inproj<300><<<nblk16, 256>>>(x_text,  Wi_text,  bi[0], batch[0], 0, n);
    k_inproj<74> <<<nblk16, 256>>>(x_audio, Wi_audio, bi[1], batch[1], 1, n);
    k_inproj<35> <<<nblk16, 256>>>(x_video, Wi_video, bi[2], batch[2], 2, n);

    // GAT layers
    for (int l = 0; l < 2; l++) {
        k_nodeproj<<<dim3(nblk16, 3), 256>>>(Wn + (size_t)l * 3 * HID * HID,
                                             bn + (size_t)l * 3 * HID, n);
        k_gat<<<dim3((n + 7) / 8, 3), 256>>>(att + (size_t)l * 9 * HID, n);
    }

    // pooling + MLP head
    k_pool<<<dim3((n + 127) / 128, 3), 64>>>(batch[0], batch[1], batch[2], n);
    k_mlp<<<1, 256>>>(Wf1, bf1, Wf2, bf2, Wf3, bf3, (float*)d_out);
}

// round 8
// speedup vs baseline: 2.4584x; 1.0831x over previous
#include <cuda_runtime.h>

#define MODS   3
#define HEADS  4
#define HID    64
#define G      256
#define MAXN   50000
#define MAXE   250000
#define PELEN  5000
#define TOTDEG (9 * MAXN)
#define SCAN_BLOCKS ((TOTDEG + 2047) / 2048)   // 220

// ---------------- scratch (device globals; no allocation allowed) ----------------
static __device__ __align__(256) float d_h  [MODS * MAXN * HID];  // layer features
static __device__ __align__(256) float d_hp [MODS * MAXN * HID];  // projected features
static __device__ __align__(16) int   d_deg    [TOTDEG];
static __device__ __align__(16) int   d_scantmp[TOTDEG];
static __device__ int   d_bsum  [SCAN_BLOCKS];
static __device__ int   d_rowptr[9 * (MAXN + 1)];
static __device__ int   d_cursor[9 * MAXN];
static __device__ int   d_esrc  [9 * MAXE];
static __device__ int   d_start [MODS * G];
static __device__ float d_pool  [G * HID];
static __device__ float d_cnt   [G];

// ---------------- init: zero degree hist + pool + start sentinel + rowptr tails ----------------
__global__ void k_init()
{
    int i = blockIdx.x * blockDim.x + threadIdx.x;
    if (i < TOTDEG)   d_deg[i] = 0;
    if (i < MODS * G) d_start[i] = 0x7fffffff;
    if (i < G * HID)  d_pool[i] = 0.f;
    if (i < G)        d_cnt[i] = 0.f;
    if (i < 9)        d_rowptr[i * (MAXN + 1) + MAXN] = MAXE;
}

__global__ void k_start_min(const int* __restrict__ b0, const int* __restrict__ b1,
                            const int* __restrict__ b2, int n)
{
    int i = blockIdx.x * blockDim.x + threadIdx.x;
    if (i >= n) return;
    const int* b = (blockIdx.y == 0) ? b0 : (blockIdx.y == 1) ? b1 : b2;
    atomicMin(&d_start[blockIdx.y * G + b[i]], i);
}

// ---------------- CSR build ----------------
__global__ void k_hist(const int* __restrict__ edges, int E)
{
    int rel = blockIdx.y;
    int e = blockIdx.x * blockDim.x + threadIdx.x;
    if (e >= E) return;
    int dN = edges[(size_t)rel * 2 * E + E + e];
    atomicAdd(&d_deg[rel * MAXN + dN], 1);
}

// phase A: per-block local exclusive scan (2048 elems/block), write block sums
__global__ void k_scanA()
{
    __shared__ int sh[256];
    int t = threadIdx.x;
    int base = blockIdx.x * 2048 + t * 8;
    int v0 = 0, v1 = 0, v2 = 0, v3 = 0, v4 = 0, v5 = 0, v6 = 0, v7 = 0;
    if (base + 7 < TOTDEG) {
        int4 a = *(const int4*)&d_deg[base];
        int4 b = *(const int4*)&d_deg[base + 4];
        v0 = a.x; v1 = a.y; v2 = a.z; v3 = a.w;
        v4 = b.x; v5 = b.y; v6 = b.z; v7 = b.w;
    } else {
        if (base + 0 < TOTDEG) v0 = d_deg[base + 0];
        if (base + 1 < TOTDEG) v1 = d_deg[base + 1];
        if (base + 2 < TOTDEG) v2 = d_deg[base + 2];
        if (base + 3 < TOTDEG) v3 = d_deg[base + 3];
        if (base + 4 < TOTDEG) v4 = d_deg[base + 4];
        if (base + 5 < TOTDEG) v5 = d_deg[base + 5];
        if (base + 6 < TOTDEG) v6 = d_deg[base + 6];
        if (base + 7 < TOTDEG) v7 = d_deg[base + 7];
    }
    int tsum = v0 + v1 + v2 + v3 + v4 + v5 + v6 + v7;
    sh[t] = tsum;
    __syncthreads();
    for (int off = 1; off < 256; off <<= 1) {
        int v = (t >= off) ? sh[t - off] : 0;
        __syncthreads();
        sh[t] += v;
        __syncthreads();
    }
    int run = sh[t] - tsum;   // exclusive offset within block
    if (t == 255) d_bsum[blockIdx.x] = sh[255];
    int w;
    w = run; run += v0; if (base + 0 < TOTDEG) d_scantmp[base + 0] = w;
    w = run; run += v1; if (base + 1 < TOTDEG) d_scantmp[base + 1] = w;
    w = run; run += v2; if (base + 2 < TOTDEG) d_scantmp[base + 2] = w;
    w = run; run += v3; if (base + 3 < TOTDEG) d_scantmp[base + 3] = w;
    w = run; run += v4; if (base + 4 < TOTDEG) d_scantmp[base + 4] = w;
    w = run; run += v5; if (base + 5 < TOTDEG) d_scantmp[base + 5] = w;
    w = run; run += v6; if (base + 6 < TOTDEG) d_scantmp[base + 6] = w;
    w = run; run += v7; if (base + 7 < TOTDEG) d_scantmp[base + 7] = w;
}

// phase B: single block scans the block sums (in place, exclusive)
__global__ void k_scanB()
{
    __shared__ int sh[256];
    int t = threadIdx.x;
    int v = (t < SCAN_BLOCKS) ? d_bsum[t] : 0;
    sh[t] = v;
    __syncthreads();
    for (int off = 1; off < 256; off <<= 1) {
        int x = (t >= off) ? sh[t - off] : 0;
        __syncthreads();
        sh[t] += x;
        __syncthreads();
    }
    if (t < SCAN_BLOCKS) d_bsum[t] = sh[t] - v;   // exclusive
}

// phase C: add block offsets, convert global prefix to per-relation rowptr/cursor
__global__ void k_scanC()
{
    int idx = blockIdx.x * blockDim.x + threadIdx.x;
    if (idx >= TOTDEG) return;
    int val = d_scantmp[idx] + d_bsum[idx >> 11];
    int rel = idx / MAXN;
    int loc = idx - rel * MAXN;
    int r = val - rel * MAXE;   // each relation has exactly E edges
    d_rowptr[rel * (MAXN + 1) + loc] = r;
    d_cursor[rel * MAXN + loc] = r;
}

__global__ void k_scatter(const int* __restrict__ edges, int E)
{
    int rel = blockIdx.y;
    int e = blockIdx.x * blockDim.x + threadIdx.x;
    if (e >= E) return;
    const int* src = edges + (size_t)rel * 2 * E;
    int sN = src[e], dN = src[E + e];
    int pos = atomicAdd(&d_cursor[rel * MAXN + dN], 1);
    d_esrc[(size_t)rel * E + pos] = sN;
}

// ---------------- input projection + PE: 32 nodes/block, 2 nodes x 4 cols per thread ----------------
template<int IN>
__global__ void k_inproj(const float* __restrict__ x, const float* __restrict__ W,
                         const float* __restrict__ b, const int* __restrict__ batch,
                         int mod, int n)
{
    __shared__ float xs[32][IN];
    int tid = threadIdx.x;
    int node0 = blockIdx.x * 32;
    for (int idx = tid; idx < 32 * IN; idx += 256) {
        int r = idx / IN, k = idx - r * IN;
        int node = node0 + r;
        xs[r][k] = (node < n) ? x[(size_t)node * IN + k] : 0.f;
    }
    __syncthreads();
    int ty = tid >> 4, tx = tid & 15;
    int na = node0 + ty * 2, nb = na + 1;

    const float4* __restrict__ W4 = (const float4*)W;
    float4 bb = ((const float4*)b)[tx];
    float4 acc0 = bb, acc1 = bb;
    const float* xa = xs[ty * 2];
    const float* xb = xs[ty * 2 + 1];
    #pragma unroll 4
    for (int k = 0; k < IN; k++) {
        float4 wv = W4[k * 16 + tx];
        float va = xa[k], vb = xb[k];
        acc0.x = fmaf(va, wv.x, acc0.x);
        acc0.y = fmaf(va, wv.y, acc0.y);
        acc0.z = fmaf(va, wv.z, acc0.z);
        acc0.w = fmaf(va, wv.w, acc0.w);
        acc1.x = fmaf(vb, wv.x, acc1.x);
        acc1.y = fmaf(vb, wv.y, acc1.y);
        acc1.z = fmaf(vb, wv.z, acc1.z);
        acc1.w = fmaf(vb, wv.w, acc1.w);
    }
    // positional encoding (R1-proven math)
    int kk0 = 2 * (2 * tx), kk1 = 2 * (2 * tx + 1);
    float div0 = expf(-(float)kk0 * (9.210340371976184f / 64.0f));
    float div1 = expf(-(float)kk1 * (9.210340371976184f / 64.0f));
    if (na < n) {
        float pf = (float)(na - d_start[mod * G + batch[na]]);
        float a0 = pf * div0, a1 = pf * div1;
        acc0.x += sinf(a0); acc0.y += cosf(a0);
        acc0.z += sinf(a1); acc0.w += cosf(a1);
        ((float4*)(d_h + ((size_t)mod * n + na) * HID))[tx] = acc0;
    }
    if (nb < n) {
        float pf = (float)(nb - d_start[mod * G + batch[nb]]);
        float a0 = pf * div0, a1 = pf * div1;
        acc1.x += sinf(a0); acc1.y += cosf(a0);
        acc1.z += sinf(a1); acc1.w += cosf(a1);
        ((float4*)(d_h + ((size_t)mod * n + nb) * HID))[tx] = acc1;
    }
}

// ---------------- node projection: W staged in smem, 2 nodes x 4 cols per thread ----------------
__global__ void k_nodeproj(const float* __restrict__ Wl, const float* __restrict__ bl, int n)
{
    __shared__ float4 Ws[HID * 16];     // 64 rows x 16 float4 = 16KB
    __shared__ float  xs[32][HID];      // 8KB
    int m = blockIdx.y;
    int tid = threadIdx.x;
    int node0 = blockIdx.x * 32;
    const float4* __restrict__ W4 = (const float4*)(Wl + m * HID * HID);
    for (int idx = tid; idx < HID * 16; idx += 256) Ws[idx] = W4[idx];
    const float* __restrict__ src = d_h + (size_t)m * n * HID;
    for (int idx = tid; idx < 32 * HID; idx += 256) {
        int r = idx >> 6, k = idx & 63;
        int node = node0 + r;
        xs[r][k] = (node < n) ? src[(size_t)node * HID + k] : 0.f;
    }
    __syncthreads();
    int ty = tid >> 4, tx = tid & 15;
    int na = node0 + ty * 2, nb = na + 1;

    float4 bb = ((const float4*)(bl + m * HID))[tx];
    float4 acc0 = bb, acc1 = bb;
    const float* xa = xs[ty * 2];
    const float* xb = xs[ty * 2 + 1];
    #pragma unroll 4
    for (int k = 0; k < HID; k++) {
        float4 wv = Ws[k * 16 + tx];
        float va = xa[k], vb = xb[k];
        acc0.x = fmaf(va, wv.x, acc0.x);
        acc0.y = fmaf(va, wv.y, acc0.y);
        acc0.z = fmaf(va, wv.z, acc0.z);
        acc0.w = fmaf(va, wv.w, acc0.w);
        acc1.x = fmaf(vb, wv.x, acc1.x);
        acc1.y = fmaf(vb, wv.y, acc1.y);
        acc1.z = fmaf(vb, wv.z, acc1.z);
        acc1.w = fmaf(vb, wv.w, acc1.w);
    }
    if (na < n) ((float4*)(d_hp + ((size_t)m * n + na) * HID))[tx] = acc0;
    if (nb < n) ((float4*)(d_hp + ((size_t)m * n + nb) * HID))[tx] = acc1;
}

// ---------------- GAT layer: warp per (dst-mod j, dst node); single-pass softmax (R7-proven) ----------------
__global__ void k_gat(const float* __restrict__ attL, int n)
{
    int wid = threadIdx.x >> 5, lane = threadIdx.x & 31;
    int dst = blockIdx.x * 8 + wid;
    if (dst >= n) return;
    int j = blockIdx.y;
    int l2 = lane * 2;

    float2 hd = *(const float2*)&d_hp[((size_t)j * n + dst) * HID + l2];
    float accx = 0.f, accy = 0.f;

    for (int i = 0; i < MODS; i++) {
        int rel = i * 3 + j;
        int rs = d_rowptr[rel * (MAXN + 1) + dst];
        int re = d_rowptr[rel * (MAXN + 1) + dst + 1];
        if (rs == re) continue;
        float2 a2 = *(const float2*)&attL[rel * HID + l2];
        const float* __restrict__ hpB = d_hp + (size_t)i * n * HID;
        const int* __restrict__ es = d_esrc + (size_t)rel * MAXE;

        float s = 0.f, ax = 0.f, ay = 0.f;
        for (int c0 = rs; c0 < re; c0 += 32) {
            int my = (c0 + lane < re) ? es[c0 + lane] : 0;
            int cnt = min(32, re - c0);
            for (int q = 0; q < cnt; q++) {
                int src = __shfl_sync(0xffffffffu, my, q);
                float2 hs = *(const float2*)&hpB[(size_t)src * HID + l2];
                float zx = hs.x + hd.x; zx = zx > 0.f ? zx : 0.2f * zx;
                float zy = hs.y + hd.y; zy = zy > 0.f ? zy : 0.2f * zy;
                float t = zx * a2.x + zy * a2.y;
                t += __shfl_xor_sync(0xffffffffu, t, 1);
                t += __shfl_xor_sync(0xffffffffu, t, 2);
                t += __shfl_xor_sync(0xffffffffu, t, 4);
                float e = __expf(t);
                s += e;
                ax = fmaf(e, hs.x, ax);
                ay = fmaf(e, hs.y, ay);
            }
        }
        float inv_s = 1.f / s;
        accx = fmaf(ax, inv_s, accx);
        accy = fmaf(ay, inv_s, accy);
    }

    float ox = accx * (1.f / 3.f); ox = ox > 0.f ? ox : 0.f;
    float oy = accy * (1.f / 3.f); oy = oy > 0.f ? oy : 0.f;
    float2 o = {ox, oy};
    *(float2*)&d_h[((size_t)j * n + dst) * HID + l2] = o;
}

// ---------------- pooling (R1-proven form) ----------------
__global__ void k_pool(const int* __restrict__ b0, const int* __restrict__ b1,
                       const int* __restrict__ b2, int n)
{
    const int CH = 128;
    int m = blockIdx.y;
    const int* batch = (m == 0) ? b0 : (m == 1) ? b1 : b2;
    const float* h = d_h + (size_t)m * n * HID;
    int i0 = blockIdx.x * CH;
    int c = threadIdx.x;
    int end = min(i0 + CH, n);
    float acc = 0.f; int cur = -1; int run = 0;
    for (int i = i0; i < end; i++) {
        int bg = batch[i];
        if (bg != cur) {
            if (cur >= 0) {
                atomicAdd(&d_pool[cur * HID + c], acc);
                if (c == 0) atomicAdd(&d_cnt[cur], (float)run);
            }
            cur = bg; acc = 0.f; run = 0;
        }
        acc += h[(size_t)i * HID + c];
        run++;
    }
    if (cur >= 0) {
        atomicAdd(&d_pool[cur * HID + c], acc);
        if (c == 0) atomicAdd(&d_cnt[cur], (float)run);
    }
}

// ---------------- readout MLP (R1-proven form) ----------------
__global__ void k_mlp(const float* __restrict__ Wf1, const float* __restrict__ bf1,
                      const float* __restrict__ Wf2, const float* __restrict__ bf2,
                      const float* __restrict__ Wf3, const float* __restrict__ bf3,
                      float* __restrict__ out)
{
    int g = threadIdx.x; // 256 threads, 1 block
    float inv = 1.f / fmaxf(d_cnt[g], 1.f);
    float y1[16];
    #pragma unroll
    for (int j = 0; j < 16; j++) y1[j] = bf1[j];
    for (int k = 0; k < HID; k++) {
        float v = d_pool[g * HID + k] * inv;
        #pragma unroll
        for (int j = 0; j < 16; j++) y1[j] = fmaf(v, Wf1[k * 16 + j], y1[j]);
    }
    float y2[16];
    #pragma unroll
    for (int j = 0; j < 16; j++) y2[j] = bf2[j];
    #pragma unroll
    for (int k = 0; k < 16; k++) {
        float v = y1[k] > 0.f ? y1[k] : 0.f;
        #pragma unroll
        for (int j = 0; j < 16; j++) y2[j] = fmaf(v, Wf2[k * 16 + j], y2[j]);
    }
    float o = bf3[0];
    #pragma unroll
    for (int j = 0; j < 16; j++) {
        float v = y2[j] > 0.f ? y2[j] : 0.f;
        o = fmaf(v, Wf3[j], o);
    }
    out[g] = o;
}

// ---------------- host launcher ----------------
extern "C" void kernel_launch(void* const* d_in, const int* in_sizes, int n_in,
                              void* d_out, int out_size)
{
    const float *x_text = 0, *x_audio = 0, *x_video = 0;
    const float *Wi_text = 0, *Wi_audio = 0, *Wi_video = 0;
    const float *bi[3] = {0, 0, 0};
    const float *Wn = 0, *bn = 0, *att = 0;
    const float *Wf1 = 0, *bf1 = 0, *Wf2 = 0, *bf2 = 0, *Wf3 = 0, *bf3 = 0;
    const int *batch[3] = {0, 0, 0};
    const int *edges = 0;
    int nb = 0, nbi = 0, n16 = 0;

    for (int i = 0; i < n_in; i++) {
        int s = in_sizes[i];
        const void* p = d_in[i];
        if      (s == 50000 * 300) x_text  = (const float*)p;
        else if (s == 50000 * 74)  x_audio = (const float*)p;
        else if (s == 50000 * 35)  x_video = (const float*)p;
        else if (s == 50000)       { if (nb < 3) batch[nb++] = (const int*)p; }
        else if (s == 9 * 2 * 250000) edges = (const int*)p;
        else if (s == 300 * 64)    Wi_text  = (const float*)p;
        else if (s == 74 * 64)     Wi_audio = (const float*)p;
        else if (s == 35 * 64)     Wi_video = (const float*)p;
        else if (s == 64)          { if (nbi < 3) bi[nbi++] = (const float*)p; }
        else if (s == 2 * 3 * 64 * 64) Wn = (const float*)p;
        else if (s == 2 * 3 * 64)  bn  = (const float*)p;
        else if (s == 2 * 9 * 64)  att = (const float*)p;
        else if (s == 64 * 16)     Wf1 = (const float*)p;
        else if (s == 16)          { if (n16 == 0) bf1 = (const float*)p;
                                     else if (n16 == 1) bf2 = (const float*)p;
                                     else Wf3 = (const float*)p; n16++; }
        else if (s == 16 * 16)     Wf2 = (const float*)p;
        else if (s == 1)           bf3 = (const float*)p;
    }

    const int n = MAXN, E = MAXE;
    const int nblk32 = (n + 31) / 32;

    // init + segment starts
    k_init<<<(TOTDEG + 255) / 256, 256>>>();
    k_start_min<<<dim3((n + 255) / 256, 3), 256>>>(batch[0], batch[1], batch[2], n);

    // CSR build (once; shared by both layers)
    k_hist<<<dim3((E + 255) / 256, 9), 256>>>(edges, E);
    k_scanA<<<SCAN_BLOCKS, 256>>>();
    k_scanB<<<1, 256>>>();
    k_scanC<<<(TOTDEG + 255) / 256, 256>>>();
    k_scatter<<<dim3((E + 255) / 256, 9), 256>>>(edges, E);

    // input projections + PE
    k_inproj<300><<<nblk32, 256>>>(x_text,  Wi_text,  bi[0], batch[0], 0, n);
    k_inproj<74> <<<nblk32, 256>>>(x_audio, Wi_audio, bi[1], batch[1], 1, n);
    k_inproj<35> <<<nblk32, 256>>>(x_video, Wi_video, bi[2], batch[2], 2, n);

    // GAT layers
    for (int l = 0; l < 2; l++) {
        k_nodeproj<<<dim3(nblk32, 3), 256>>>(Wn + (size_t)l * 3 * HID * HID,
                                             bn + (size_t)l * 3 * HID, n);
        k_gat<<<dim3((n + 7) / 8, 3), 256>>>(att + (size_t)l * 9 * HID, n);
    }

    // pooling + MLP head
    k_pool<<<dim3((n + 127) / 128, 3), 64>>>(batch[0], batch[1], batch[2], n);
    k_mlp<<<1, 256>>>(Wf1, bf1, Wf2, bf2, Wf3, bf3, (float*)d_out);
}